// round 16
// baseline (speedup 1.0000x reference)
#include <cuda_runtime.h>
#include <cuda_bf16.h>
#include <cuda_fp16.h>
#include <cstdint>

#define NN 100000
#define EE 1600000
#define D  128
#define KTOT 384
#define NB  ((NN + 1023) / 1024)            // 98 scan blocks (all resident)
#define XBLOCKS ((NN * D / 8 + 255) / 256)  // 6250 xconv blocks
#define WBLOCKS ((128 * KTOT + 255) / 256)  // 192 wconv blocks
#define HBLOCKS ((EE / 4 + 255) / 256)      // 1563 hist blocks

typedef unsigned long long ull;

// ---------------- scratch (static device globals; no allocation) -------------
__device__ __align__(16) __half g_xh[(size_t)NN * D];   // fp16 image of x
__device__ __align__(16) __half g_f1[(size_t)NN * D];   // hop-1 (fp16)
__device__ __align__(16) __half g_f2[(size_t)NN * D];   // hop-2 (fp16)
__device__ int   g_deg[NN];
__device__ int   g_rowptr[NN + 1];
__device__ ull   g_scan_state[NB];      // packed (flag<<32)|blocksum
__device__ int   g_rank[EE];            // per-edge arrival rank within src node
__device__ int2  g_dstval[EE];          // packed (dst, val-bits)
// Pre-swizzled fp16 image of W: 6 K-chunks of [128 n][64 k] fp16 (16 KB each)
__device__ __align__(16) unsigned char g_Wh[6 * 16384];

// ---------------- PTX helpers -------------------------------------------------
__device__ __forceinline__ uint32_t smem_u32(const void* p) {
    uint32_t a;
    asm("{ .reg .u64 t; cvta.to.shared.u64 t, %1; cvt.u32.u64 %0, t; }" : "=r"(a) : "l"(p));
    return a;
}

#define LDSM4(R, A)                                                         \
    asm volatile("ldmatrix.sync.aligned.m8n8.x4.shared.b16 "                \
                 "{%0,%1,%2,%3}, [%4];"                                     \
                 : "=r"((R)[0]), "=r"((R)[1]), "=r"((R)[2]), "=r"((R)[3])   \
                 : "r"(A))

#define MMAF16(DD, AA, B0, B1)                                              \
    asm volatile("mma.sync.aligned.m16n8k16.row.col.f32.f16.f16.f32 "       \
                 "{%0,%1,%2,%3},{%4,%5,%6,%7},{%8,%9},{%0,%1,%2,%3};"       \
                 : "+f"((DD)[0]), "+f"((DD)[1]), "+f"((DD)[2]), "+f"((DD)[3]) \
                 : "r"((AA)[0]), "r"((AA)[1]), "r"((AA)[2]), "r"((AA)[3]),  \
                   "r"(B0), "r"(B1))

#define CP_ASYNC16(dst, src, sz)                                            \
    asm volatile("cp.async.ca.shared.global [%0], [%1], 16, %2;"            \
                 :: "r"(dst), "l"(src), "r"(sz))
#define CP_COMMIT() asm volatile("cp.async.commit_group;" ::: "memory")
#define CP_WAIT(n)  asm volatile("cp.async.wait_group %0;" :: "n"(n) : "memory")

__device__ __forceinline__ uint32_t swz(uint32_t bo) {
    return bo ^ ((bo >> 3) & 0x70);
}

__device__ __forceinline__ int warp_incl_scan(int val, int lane) {
    #pragma unroll
    for (int off = 1; off < 32; off <<= 1) {
        int t = __shfl_up_sync(0xffffffffu, val, off);
        if (lane >= off) val += t;
    }
    return val;
}

// ------ fused prep: x->fp16 | W->swizzled fp16 (+zero scan state) | hist -----
__global__ void prep_hist_kernel(const float4* __restrict__ x4,
                                 const float* __restrict__ W,
                                 const int* __restrict__ src) {
    if (blockIdx.x < XBLOCKS) {
        int i = blockIdx.x * 256 + threadIdx.x;      // over NN*D/8
        if (i >= NN * D / 8) return;
        float4 a = __ldg(&x4[i * 2]);
        float4 b = __ldg(&x4[i * 2 + 1]);
        __half2 h0 = __float22half2_rn(make_float2(a.x, a.y));
        __half2 h1 = __float22half2_rn(make_float2(a.z, a.w));
        __half2 h2 = __float22half2_rn(make_float2(b.x, b.y));
        __half2 h3 = __float22half2_rn(make_float2(b.z, b.w));
        uint4 o;
        o.x = *(uint32_t*)&h0; o.y = *(uint32_t*)&h1;
        o.z = *(uint32_t*)&h2; o.w = *(uint32_t*)&h3;
        ((uint4*)g_xh)[i] = o;
    } else if (blockIdx.x < XBLOCKS + WBLOCKS) {
        int bi = blockIdx.x - XBLOCKS;
        // re-zero the scan handshake words every run (graph-replay safe:
        // this kernel completes before the scan kernel launches)
        if (bi == 0 && threadIdx.x < NB) g_scan_state[threadIdx.x] = 0ull;
        int i = bi * 256 + threadIdx.x;              // over 128*384
        if (i >= 128 * KTOT) return;
        int n = i / KTOT, k = i % KTOT;
        __half h = __float2half_rn(W[i]);
        int c = k >> 6, kk = k & 63;
        uint32_t sw = swz((uint32_t)n * 128 + kk * 2);
        *(__half*)(g_Wh + c * 16384 + sw) = h;
    } else {
        int t = (blockIdx.x - XBLOCKS - WBLOCKS) * 256 + threadIdx.x;
        int e = t * 4;
        if (e + 3 < EE) {
            int4 s = __ldg((const int4*)(src + e));
            int4 r;
            r.x = atomicAdd(&g_deg[s.x], 1);
            r.y = atomicAdd(&g_deg[s.y], 1);
            r.z = atomicAdd(&g_deg[s.z], 1);
            r.w = atomicAdd(&g_deg[s.w], 1);
            *(int4*)(g_rank + e) = r;
        } else {
            for (int q = e; q < EE; q++)
                g_rank[q] = atomicAdd(&g_deg[__ldg(src + q)], 1);
        }
    }
}

// ---- single-kernel scan: 98 all-resident blocks, packed-word aggregates ----
__global__ __launch_bounds__(1024)
void scan_kernel() {
    __shared__ int warpsums[32];
    __shared__ int red[32];
    __shared__ int s_pref;
    int tid = threadIdx.x, lane = tid & 31, wid = tid >> 5;
    int b = blockIdx.x;
    int i = b * 1024 + tid;

    int v = (i < NN) ? g_deg[i] : 0;
    int val = warp_incl_scan(v, lane);
    if (lane == 31) warpsums[wid] = val;
    __syncthreads();
    if (wid == 0) warpsums[lane] = warp_incl_scan(warpsums[lane], lane);
    __syncthreads();
    int excl  = val - v + (wid > 0 ? warpsums[wid - 1] : 0);
    int total = warpsums[31];

    // Post own aggregate (single 64-bit word -> no separate fence needed)
    if (tid == 0)
        atomicExch(&g_scan_state[b], (1ull << 32) | (unsigned)total);

    // First NB threads spin on one aggregate each; sum those before us.
    int contrib = 0;
    if (tid < NB) {
        ull w;
        do { w = atomicAdd(&g_scan_state[tid], 0ull); } while ((w >> 32) == 0);
        if (tid < b) contrib = (int)(w & 0xffffffffu);
    }
    int s = contrib;
    #pragma unroll
    for (int off = 16; off > 0; off >>= 1)
        s += __shfl_down_sync(0xffffffffu, s, off);
    if (lane == 0) red[wid] = s;
    __syncthreads();
    if (wid == 0) {
        int t2 = red[lane];
        #pragma unroll
        for (int off = 16; off > 0; off >>= 1)
            t2 += __shfl_down_sync(0xffffffffu, t2, off);
        if (lane == 0) s_pref = t2;
    }
    __syncthreads();

    if (i < NN) g_rowptr[i] = excl + s_pref;
    if (i == 0) g_rowptr[NN] = EE;
}

// Atomic-free scatter: position = rowptr[src] + rank (rank saved during hist)
__global__ void scatter_kernel(const int* __restrict__ src,
                               const int* __restrict__ dst,
                               const float* __restrict__ val) {
    int t = blockIdx.x * blockDim.x + threadIdx.x;
    int e = t * 4;
    if (e + 3 < EE) {
        int4   s = __ldg((const int4*)(src + e));
        int4   r = *(const int4*)(g_rank + e);
        int4   d = __ldg((const int4*)(dst + e));
        float4 v = __ldg((const float4*)(val + e));
        g_dstval[__ldg(&g_rowptr[s.x]) + r.x] = make_int2(d.x, __float_as_int(v.x));
        g_dstval[__ldg(&g_rowptr[s.y]) + r.y] = make_int2(d.y, __float_as_int(v.y));
        g_dstval[__ldg(&g_rowptr[s.z]) + r.z] = make_int2(d.z, __float_as_int(v.z));
        g_dstval[__ldg(&g_rowptr[s.w]) + r.w] = make_int2(d.w, __float_as_int(v.w));
    } else {
        for (int q = e; q < EE; q++) {
            int ss = __ldg(src + q);
            g_dstval[__ldg(&g_rowptr[ss]) + g_rank[q]] =
                make_int2(__ldg(dst + q), __float_as_int(__ldg(val + q)));
        }
    }
}

// ---- SpMM (fp16 rows): HALF-warp per row, uint4 (16B) lanes, 8-deep unroll --
__global__ __launch_bounds__(256)
void spmm_kernel(const uint4* __restrict__ fin, uint4* __restrict__ fout) {
    int hw   = (blockIdx.x * blockDim.x + threadIdx.x) >> 4;  // half-warp id
    int lane = threadIdx.x & 15;
    if (hw >= NN) return;
    int beg = __ldg(&g_rowptr[hw]);
    int end = __ldg(&g_rowptr[hw + 1]);

    float acc[8] = {0.f, 0.f, 0.f, 0.f, 0.f, 0.f, 0.f, 0.f};
    int j = beg;
    for (; j + 8 <= end; j += 8) {
        int2 m[8];
        uint4 a[8];
        #pragma unroll
        for (int q = 0; q < 8; q++) m[q] = __ldg(&g_dstval[j + q]);
        #pragma unroll
        for (int q = 0; q < 8; q++) a[q] = __ldg(&fin[(size_t)m[q].x * 16 + lane]);
        #pragma unroll
        for (int q = 0; q < 8; q++) {
            float v = __int_as_float(m[q].y);
            float2 f0 = __half22float2(*(__half2*)&a[q].x);
            float2 f1 = __half22float2(*(__half2*)&a[q].y);
            float2 f2 = __half22float2(*(__half2*)&a[q].z);
            float2 f3 = __half22float2(*(__half2*)&a[q].w);
            acc[0] = fmaf(v, f0.x, acc[0]);
            acc[1] = fmaf(v, f0.y, acc[1]);
            acc[2] = fmaf(v, f1.x, acc[2]);
            acc[3] = fmaf(v, f1.y, acc[3]);
            acc[4] = fmaf(v, f2.x, acc[4]);
            acc[5] = fmaf(v, f2.y, acc[5]);
            acc[6] = fmaf(v, f3.x, acc[6]);
            acc[7] = fmaf(v, f3.y, acc[7]);
        }
    }
    if (j + 4 <= end) {
        int2 m[4];
        uint4 a[4];
        #pragma unroll
        for (int q = 0; q < 4; q++) m[q] = __ldg(&g_dstval[j + q]);
        #pragma unroll
        for (int q = 0; q < 4; q++) a[q] = __ldg(&fin[(size_t)m[q].x * 16 + lane]);
        #pragma unroll
        for (int q = 0; q < 4; q++) {
            float v = __int_as_float(m[q].y);
            float2 f0 = __half22float2(*(__half2*)&a[q].x);
            float2 f1 = __half22float2(*(__half2*)&a[q].y);
            float2 f2 = __half22float2(*(__half2*)&a[q].z);
            float2 f3 = __half22float2(*(__half2*)&a[q].w);
            acc[0] = fmaf(v, f0.x, acc[0]);
            acc[1] = fmaf(v, f0.y, acc[1]);
            acc[2] = fmaf(v, f1.x, acc[2]);
            acc[3] = fmaf(v, f1.y, acc[3]);
            acc[4] = fmaf(v, f2.x, acc[4]);
            acc[5] = fmaf(v, f2.y, acc[5]);
            acc[6] = fmaf(v, f3.x, acc[6]);
            acc[7] = fmaf(v, f3.y, acc[7]);
        }
        j += 4;
    }
    for (; j < end; j++) {
        int2 m = __ldg(&g_dstval[j]);
        float v = __int_as_float(m.y);
        uint4 a = __ldg(&fin[(size_t)m.x * 16 + lane]);
        float2 f0 = __half22float2(*(__half2*)&a.x);
        float2 f1 = __half22float2(*(__half2*)&a.y);
        float2 f2 = __half22float2(*(__half2*)&a.z);
        float2 f3 = __half22float2(*(__half2*)&a.w);
        acc[0] = fmaf(v, f0.x, acc[0]);
        acc[1] = fmaf(v, f0.y, acc[1]);
        acc[2] = fmaf(v, f1.x, acc[2]);
        acc[3] = fmaf(v, f1.y, acc[3]);
        acc[4] = fmaf(v, f2.x, acc[4]);
        acc[5] = fmaf(v, f2.y, acc[5]);
        acc[6] = fmaf(v, f3.x, acc[6]);
        acc[7] = fmaf(v, f3.y, acc[7]);
    }
    __half2 o0 = __float22half2_rn(make_float2(acc[0], acc[1]));
    __half2 o1 = __float22half2_rn(make_float2(acc[2], acc[3]));
    __half2 o2 = __float22half2_rn(make_float2(acc[4], acc[5]));
    __half2 o3 = __float22half2_rn(make_float2(acc[6], acc[7]));
    uint4 o;
    o.x = *(uint32_t*)&o0; o.y = *(uint32_t*)&o1;
    o.z = *(uint32_t*)&o2; o.w = *(uint32_t*)&o3;
    fout[(size_t)hw * 16 + lane] = o;
}

// ---------------- mma.sync GEMM, cp.async 3-stage pipeline --------------------
#define STAGE_BYTES 32768
#define SMEM_GEMM_BYTES (1024 + 3 * STAGE_BYTES)

__global__ __launch_bounds__(256, 2)
void gemm_mma_kernel(const float* __restrict__ bias,
                     float* __restrict__ out) {
    extern __shared__ unsigned char dsm[];
    const int tid  = threadIdx.x;
    const int lane = tid & 31;
    const int wid  = tid >> 5;
    const int warp_m = wid & 3;
    const int warp_n = wid >> 2;
    const int rbase  = blockIdx.x * 128;

    uint32_t sb0  = smem_u32(dsm);
    uint32_t base = (sb0 + 1023) & ~1023u;

    auto issue_chunk = [&](int c, int buf) {
        const uint4* fsrc = (const uint4*)((c < 2) ? g_xh : (c < 4) ? g_f1 : g_f2);
        int koff = (c & 1) * 8;                       // uint4 (16B) offset in row
        uint32_t abase = base + buf * STAGE_BYTES;
        #pragma unroll
        for (int it = 0; it < 4; it++) {
            int idx = tid + it * 256;                 // 1024 x 16B
            int row = idx >> 3, c8 = idx & 7;
            int grow = rbase + row;
            const uint4* src = fsrc + ((grow < NN) ? ((size_t)grow * 16 + koff + c8) : 0);
            CP_ASYNC16(abase + swz((uint32_t)row * 128 + c8 * 16), src,
                       (grow < NN) ? 16 : 0);
        }
        const uint4* wh = (const uint4*)(g_Wh + c * 16384);
        uint32_t bbase = abase + 16384;
        #pragma unroll
        for (int it = 0; it < 4; it++) {
            int i = tid + it * 256;
            CP_ASYNC16(bbase + i * 16, wh + i, 16);
        }
    };

    float acc[2][8][4];
    #pragma unroll
    for (int mf = 0; mf < 2; mf++)
        #pragma unroll
        for (int nf = 0; nf < 8; nf++)
            #pragma unroll
            for (int q = 0; q < 4; q++) acc[mf][nf][q] = 0.f;

    const int g = lane >> 3, r = lane & 7;
    const int a_row_off = r + (g & 1) * 8;
    const int a_k_off   = (g >> 1) * 8;
    const int b_n_off   = r + (g >> 1) * 8;
    const int b_k_off   = (g & 1) * 8;

    issue_chunk(0, 0);
    CP_COMMIT();
    issue_chunk(1, 1);
    CP_COMMIT();

    #pragma unroll
    for (int c = 0; c < 6; c++) {
        if (c + 2 < 6) {
            issue_chunk(c + 2, (c + 2) % 3);
            CP_COMMIT();
            CP_WAIT(2);
        } else if (c + 1 < 6) {
            CP_WAIT(1);
        } else {
            CP_WAIT(0);
        }
        __syncthreads();
        const uint32_t At = base + (c % 3) * STAGE_BYTES;
        const uint32_t Bh = At + 16384;
        #pragma unroll
        for (int ks = 0; ks < 4; ks++) {
            const int k0 = ks * 16;
            uint32_t ah[2][4];
            #pragma unroll
            for (int mf = 0; mf < 2; mf++) {
                uint32_t sw = swz((uint32_t)(warp_m * 32 + mf * 16 + a_row_off) * 128
                                  + (k0 + a_k_off) * 2);
                LDSM4(ah[mf], At + sw);
            }
            #pragma unroll
            for (int bq = 0; bq < 4; bq++) {
                uint32_t sw = swz((uint32_t)(warp_n * 64 + bq * 16 + b_n_off) * 128
                                  + (k0 + b_k_off) * 2);
                uint32_t bh[4];
                LDSM4(bh, Bh + sw);
                #pragma unroll
                for (int mf = 0; mf < 2; mf++) {
                    MMAF16(acc[mf][bq * 2 + 0], ah[mf], bh[0], bh[1]);
                    MMAF16(acc[mf][bq * 2 + 1], ah[mf], bh[2], bh[3]);
                }
            }
        }
        __syncthreads();
    }

    // ---- epilogue: bias + store ----
    const int qrow = lane >> 2, qcol = (lane & 3) * 2;
    #pragma unroll
    for (int nf = 0; nf < 8; nf++) {
        int col = warp_n * 64 + nf * 8 + qcol;
        float b0 = __ldg(&bias[col]);
        float b1 = __ldg(&bias[col + 1]);
        #pragma unroll
        for (int mf = 0; mf < 2; mf++) {
            int row0 = rbase + warp_m * 32 + mf * 16 + qrow;
            if (row0 < NN)
                *(float2*)(out + (size_t)row0 * 128 + col) =
                    make_float2(acc[mf][nf][0] + b0, acc[mf][nf][1] + b1);
            int row1 = row0 + 8;
            if (row1 < NN)
                *(float2*)(out + (size_t)row1 * 128 + col) =
                    make_float2(acc[mf][nf][2] + b0, acc[mf][nf][3] + b1);
        }
    }
}

// ---------------- launch ------------------------------------------------------
extern "C" void kernel_launch(void* const* d_in, const int* in_sizes, int n_in,
                              void* d_out, int out_size) {
    const float* x        = (const float*)d_in[0];
    const int*   edge_src = (const int*)  d_in[1];
    const int*   edge_dst = (const int*)  d_in[2];
    const float* edge_val = (const float*)d_in[3];
    const float* W        = (const float*)d_in[4];
    const float* b        = (const float*)d_in[5];
    float* out = (float*)d_out;

    static bool attr_set = false;
    static void* degp = nullptr;
    if (!attr_set) {
        cudaFuncSetAttribute(gemm_mma_kernel,
                             cudaFuncAttributeMaxDynamicSharedMemorySize,
                             SMEM_GEMM_BYTES);
        cudaGetSymbolAddress(&degp, g_deg);
        attr_set = true;
    }

    uint4 *xhp, *f1p, *f2p;
    cudaGetSymbolAddress((void**)&xhp, g_xh);
    cudaGetSymbolAddress((void**)&f1p, g_f1);
    cudaGetSymbolAddress((void**)&f2p, g_f2);

    // 1) memset deg, fused prep (conversions + histogram/rank + scan-state
    //    zeroing), one-shot scan, atomic-free scatter
    cudaMemsetAsync(degp, 0, NN * sizeof(int));
    prep_hist_kernel<<<XBLOCKS + WBLOCKS + HBLOCKS, 256>>>((const float4*)x, W,
                                                           edge_src);
    scan_kernel<<<NB, 1024>>>();
    scatter_kernel<<<(EE / 4 + 255) / 256, 256>>>(edge_src, edge_dst, edge_val);

    // 2) Two SpMM hops (fp16 gather, fp32 accumulate) — half-warp per row
    int spmm_blocks = (NN + 15) / 16;
    spmm_kernel<<<spmm_blocks, 256>>>(xhp, f1p);
    spmm_kernel<<<spmm_blocks, 256>>>(f1p, f2p);

    // 3) Tensor-core dense layer, cp.async 3-stage pipeline
    gemm_mma_kernel<<<(NN + 127) / 128, 256, SMEM_GEMM_BYTES>>>(b, out);
}

// round 17
// speedup vs baseline: 1.0193x; 1.0193x over previous
#include <cuda_runtime.h>
#include <cuda_bf16.h>
#include <cuda_fp16.h>
#include <cstdint>

#define NN 100000
#define EE 1600000
#define D  128
#define KTOT 384
#define NB  ((NN + 1023) / 1024)            // 98 scan blocks
#define XBLOCKS ((NN * D / 8 + 255) / 256)  // 6250 xconv blocks
#define WBLOCKS ((128 * KTOT + 255) / 256)  // 192 wconv blocks
#define HBLOCKS ((EE / 4 + 255) / 256)      // 1563 hist blocks

typedef unsigned long long ull;

// ---------------- scratch (static device globals; no allocation) -------------
__device__ __align__(16) __half g_xh[(size_t)NN * D];   // fp16 image of x
__device__ __align__(16) __half g_f1[(size_t)NN * D];   // hop-1 (fp16)
__device__ __align__(16) __half g_f2[(size_t)NN * D];   // hop-2 (fp16)
__device__ int   g_deg[NN];
__device__ int   g_rowptr[NN + 1];
__device__ int   g_blocksum[NB];
__device__ int   g_rank[EE];            // per-edge arrival rank within src node
__device__ int2  g_dstval[EE];          // packed (dst BYTE OFFSET, val-bits)
// Pre-swizzled fp16 image of W: 6 K-chunks of [128 n][64 k] fp16 (16 KB each)
__device__ __align__(16) unsigned char g_Wh[6 * 16384];

// ---------------- PTX helpers -------------------------------------------------
__device__ __forceinline__ uint32_t smem_u32(const void* p) {
    uint32_t a;
    asm("{ .reg .u64 t; cvta.to.shared.u64 t, %1; cvt.u32.u64 %0, t; }" : "=r"(a) : "l"(p));
    return a;
}

#define LDSM4(R, A)                                                         \
    asm volatile("ldmatrix.sync.aligned.m8n8.x4.shared.b16 "                \
                 "{%0,%1,%2,%3}, [%4];"                                     \
                 : "=r"((R)[0]), "=r"((R)[1]), "=r"((R)[2]), "=r"((R)[3])   \
                 : "r"(A))

#define MMAF16(DD, AA, B0, B1)                                              \
    asm volatile("mma.sync.aligned.m16n8k16.row.col.f32.f16.f16.f32 "       \
                 "{%0,%1,%2,%3},{%4,%5,%6,%7},{%8,%9},{%0,%1,%2,%3};"       \
                 : "+f"((DD)[0]), "+f"((DD)[1]), "+f"((DD)[2]), "+f"((DD)[3]) \
                 : "r"((AA)[0]), "r"((AA)[1]), "r"((AA)[2]), "r"((AA)[3]),  \
                   "r"(B0), "r"(B1))

#define CP_ASYNC16(dst, src, sz)                                            \
    asm volatile("cp.async.ca.shared.global [%0], [%1], 16, %2;"            \
                 :: "r"(dst), "l"(src), "r"(sz))
#define CP_COMMIT() asm volatile("cp.async.commit_group;" ::: "memory")
#define CP_WAIT(n)  asm volatile("cp.async.wait_group %0;" :: "n"(n) : "memory")

__device__ __forceinline__ uint32_t swz(uint32_t bo) {
    return bo ^ ((bo >> 3) & 0x70);
}

__device__ __forceinline__ int warp_incl_scan(int val, int lane) {
    #pragma unroll
    for (int off = 1; off < 32; off <<= 1) {
        int t = __shfl_up_sync(0xffffffffu, val, off);
        if (lane >= off) val += t;
    }
    return val;
}

// ------ fused prep: x->fp16 | W->swizzled fp16 | edge histogram + rank -------
__global__ void prep_hist_kernel(const float4* __restrict__ x4,
                                 const float* __restrict__ W,
                                 const int* __restrict__ src) {
    if (blockIdx.x < XBLOCKS) {
        int i = blockIdx.x * 256 + threadIdx.x;      // over NN*D/8
        if (i >= NN * D / 8) return;
        float4 a = __ldg(&x4[i * 2]);
        float4 b = __ldg(&x4[i * 2 + 1]);
        __half2 h0 = __float22half2_rn(make_float2(a.x, a.y));
        __half2 h1 = __float22half2_rn(make_float2(a.z, a.w));
        __half2 h2 = __float22half2_rn(make_float2(b.x, b.y));
        __half2 h3 = __float22half2_rn(make_float2(b.z, b.w));
        uint4 o;
        o.x = *(uint32_t*)&h0; o.y = *(uint32_t*)&h1;
        o.z = *(uint32_t*)&h2; o.w = *(uint32_t*)&h3;
        ((uint4*)g_xh)[i] = o;
    } else if (blockIdx.x < XBLOCKS + WBLOCKS) {
        int i = (blockIdx.x - XBLOCKS) * 256 + threadIdx.x;   // over 128*384
        if (i >= 128 * KTOT) return;
        int n = i / KTOT, k = i % KTOT;
        __half h = __float2half_rn(W[i]);
        int c = k >> 6, kk = k & 63;
        uint32_t sw = swz((uint32_t)n * 128 + kk * 2);
        *(__half*)(g_Wh + c * 16384 + sw) = h;
    } else {
        int t = (blockIdx.x - XBLOCKS - WBLOCKS) * 256 + threadIdx.x;
        int e = t * 4;
        if (e + 3 < EE) {
            int4 s = __ldg((const int4*)(src + e));
            int4 r;
            r.x = atomicAdd(&g_deg[s.x], 1);
            r.y = atomicAdd(&g_deg[s.y], 1);
            r.z = atomicAdd(&g_deg[s.z], 1);
            r.w = atomicAdd(&g_deg[s.w], 1);
            *(int4*)(g_rank + e) = r;
        } else {
            for (int q = e; q < EE; q++)
                g_rank[q] = atomicAdd(&g_deg[__ldg(src + q)], 1);
        }
    }
}

// ---------------- CSR scan (two-kernel version — R15 proven) -----------------
__global__ __launch_bounds__(1024)
void scan_local_kernel() {
    __shared__ int warpsums[32];
    int tid = threadIdx.x, lane = tid & 31, wid = tid >> 5;
    int i = blockIdx.x * 1024 + tid;
    int v = (i < NN) ? g_deg[i] : 0;
    int val = warp_incl_scan(v, lane);
    if (lane == 31) warpsums[wid] = val;
    __syncthreads();
    if (wid == 0) warpsums[lane] = warp_incl_scan(warpsums[lane], lane);
    __syncthreads();
    int excl = val - v + (wid > 0 ? warpsums[wid - 1] : 0);
    if (i < NN) g_rowptr[i] = excl;
    if (tid == 0) g_blocksum[blockIdx.x] = warpsums[31];
}

__global__ __launch_bounds__(256)
void scan_add_kernel() {
    __shared__ int ws[4];
    __shared__ int boff[NB];
    int tid = threadIdx.x, lane = tid & 31, wid = tid >> 5;
    int v = 0, val = 0;
    if (tid < 128) {
        v = (tid < NB) ? g_blocksum[tid] : 0;
        val = warp_incl_scan(v, lane);
        if (lane == 31) ws[wid] = val;
    }
    __syncthreads();
    if (tid == 0) {
        int a = ws[0];
        ws[0] = 0;
        #pragma unroll
        for (int q = 1; q < 4; q++) { int t = ws[q]; ws[q] = a; a += t; }
    }
    __syncthreads();
    if (tid < NB) boff[tid] = val - v + ws[wid];
    __syncthreads();
    int i = blockIdx.x * 256 + tid;
    if (i < NN) g_rowptr[i] += boff[i >> 10];
    if (i == 0) g_rowptr[NN] = EE;
}

// Atomic-free scatter; stores dst as BYTE OFFSET (dst*256) for cheap SpMM addr
__global__ void scatter_kernel(const int* __restrict__ src,
                               const int* __restrict__ dst,
                               const float* __restrict__ val) {
    int t = blockIdx.x * blockDim.x + threadIdx.x;
    int e = t * 4;
    if (e + 3 < EE) {
        int4   s = __ldg((const int4*)(src + e));
        int4   r = *(const int4*)(g_rank + e);
        int4   d = __ldg((const int4*)(dst + e));
        float4 v = __ldg((const float4*)(val + e));
        g_dstval[__ldg(&g_rowptr[s.x]) + r.x] = make_int2(d.x << 8, __float_as_int(v.x));
        g_dstval[__ldg(&g_rowptr[s.y]) + r.y] = make_int2(d.y << 8, __float_as_int(v.y));
        g_dstval[__ldg(&g_rowptr[s.z]) + r.z] = make_int2(d.z << 8, __float_as_int(v.z));
        g_dstval[__ldg(&g_rowptr[s.w]) + r.w] = make_int2(d.w << 8, __float_as_int(v.w));
    } else {
        for (int q = e; q < EE; q++) {
            int ss = __ldg(src + q);
            g_dstval[__ldg(&g_rowptr[ss]) + g_rank[q]] =
                make_int2(__ldg(dst + q) << 8, __float_as_int(__ldg(val + q)));
        }
    }
}

// ---- SpMM (fp16 rows): HALF-warp per row, byte-offset addressing ------------
__global__ __launch_bounds__(256)
void spmm_kernel(const uint4* __restrict__ fin, uint4* __restrict__ fout) {
    int hw   = (blockIdx.x * blockDim.x + threadIdx.x) >> 4;  // half-warp id
    int lane = threadIdx.x & 15;
    if (hw >= NN) return;
    int beg = __ldg(&g_rowptr[hw]);
    int end = __ldg(&g_rowptr[hw + 1]);
    const char* fb = (const char*)fin + (lane << 4);   // lane byte offset hoisted

    float acc[8] = {0.f, 0.f, 0.f, 0.f, 0.f, 0.f, 0.f, 0.f};
    int j = beg;
    for (; j + 8 <= end; j += 8) {
        int2 m[8];
        uint4 a[8];
        #pragma unroll
        for (int q = 0; q < 8; q++) m[q] = __ldg(&g_dstval[j + q]);
        #pragma unroll
        for (int q = 0; q < 8; q++)
            a[q] = __ldg((const uint4*)(fb + (uint32_t)m[q].x));
        #pragma unroll
        for (int q = 0; q < 8; q++) {
            float v = __int_as_float(m[q].y);
            float2 f0 = __half22float2(*(__half2*)&a[q].x);
            float2 f1 = __half22float2(*(__half2*)&a[q].y);
            float2 f2 = __half22float2(*(__half2*)&a[q].z);
            float2 f3 = __half22float2(*(__half2*)&a[q].w);
            acc[0] = fmaf(v, f0.x, acc[0]);
            acc[1] = fmaf(v, f0.y, acc[1]);
            acc[2] = fmaf(v, f1.x, acc[2]);
            acc[3] = fmaf(v, f1.y, acc[3]);
            acc[4] = fmaf(v, f2.x, acc[4]);
            acc[5] = fmaf(v, f2.y, acc[5]);
            acc[6] = fmaf(v, f3.x, acc[6]);
            acc[7] = fmaf(v, f3.y, acc[7]);
        }
    }
    if (j + 4 <= end) {
        int2 m[4];
        uint4 a[4];
        #pragma unroll
        for (int q = 0; q < 4; q++) m[q] = __ldg(&g_dstval[j + q]);
        #pragma unroll
        for (int q = 0; q < 4; q++)
            a[q] = __ldg((const uint4*)(fb + (uint32_t)m[q].x));
        #pragma unroll
        for (int q = 0; q < 4; q++) {
            float v = __int_as_float(m[q].y);
            float2 f0 = __half22float2(*(__half2*)&a[q].x);
            float2 f1 = __half22float2(*(__half2*)&a[q].y);
            float2 f2 = __half22float2(*(__half2*)&a[q].z);
            float2 f3 = __half22float2(*(__half2*)&a[q].w);
            acc[0] = fmaf(v, f0.x, acc[0]);
            acc[1] = fmaf(v, f0.y, acc[1]);
            acc[2] = fmaf(v, f1.x, acc[2]);
            acc[3] = fmaf(v, f1.y, acc[3]);
            acc[4] = fmaf(v, f2.x, acc[4]);
            acc[5] = fmaf(v, f2.y, acc[5]);
            acc[6] = fmaf(v, f3.x, acc[6]);
            acc[7] = fmaf(v, f3.y, acc[7]);
        }
        j += 4;
    }
    for (; j < end; j++) {
        int2 m = __ldg(&g_dstval[j]);
        float v = __int_as_float(m.y);
        uint4 a = __ldg((const uint4*)(fb + (uint32_t)m.x));
        float2 f0 = __half22float2(*(__half2*)&a.x);
        float2 f1 = __half22float2(*(__half2*)&a.y);
        float2 f2 = __half22float2(*(__half2*)&a.z);
        float2 f3 = __half22float2(*(__half2*)&a.w);
        acc[0] = fmaf(v, f0.x, acc[0]);
        acc[1] = fmaf(v, f0.y, acc[1]);
        acc[2] = fmaf(v, f1.x, acc[2]);
        acc[3] = fmaf(v, f1.y, acc[3]);
        acc[4] = fmaf(v, f2.x, acc[4]);
        acc[5] = fmaf(v, f2.y, acc[5]);
        acc[6] = fmaf(v, f3.x, acc[6]);
        acc[7] = fmaf(v, f3.y, acc[7]);
    }
    __half2 o0 = __float22half2_rn(make_float2(acc[0], acc[1]));
    __half2 o1 = __float22half2_rn(make_float2(acc[2], acc[3]));
    __half2 o2 = __float22half2_rn(make_float2(acc[4], acc[5]));
    __half2 o3 = __float22half2_rn(make_float2(acc[6], acc[7]));
    uint4 o;
    o.x = *(uint32_t*)&o0; o.y = *(uint32_t*)&o1;
    o.z = *(uint32_t*)&o2; o.w = *(uint32_t*)&o3;
    fout[(size_t)hw * 16 + lane] = o;
}

// ---------------- mma.sync GEMM, cp.async double-buffered (R15 proven) -------
#define STAGE_BYTES 32768
#define SMEM_GEMM_BYTES (1024 + 2 * STAGE_BYTES)

__global__ __launch_bounds__(256, 2)
void gemm_mma_kernel(const float* __restrict__ bias,
                     float* __restrict__ out) {
    extern __shared__ unsigned char dsm[];
    const int tid  = threadIdx.x;
    const int lane = tid & 31;
    const int wid  = tid >> 5;
    const int warp_m = wid & 3;
    const int warp_n = wid >> 2;
    const int rbase  = blockIdx.x * 128;

    uint32_t sb0  = smem_u32(dsm);
    uint32_t base = (sb0 + 1023) & ~1023u;

    auto issue_chunk = [&](int c, int buf) {
        const uint4* fsrc = (const uint4*)((c < 2) ? g_xh : (c < 4) ? g_f1 : g_f2);
        int koff = (c & 1) * 8;                       // uint4 (16B) offset in row
        uint32_t abase = base + buf * STAGE_BYTES;
        #pragma unroll
        for (int it = 0; it < 4; it++) {
            int idx = tid + it * 256;                 // 1024 x 16B
            int row = idx >> 3, c8 = idx & 7;
            int grow = rbase + row;
            const uint4* src = fsrc + ((grow < NN) ? ((size_t)grow * 16 + koff + c8) : 0);
            CP_ASYNC16(abase + swz((uint32_t)row * 128 + c8 * 16), src,
                       (grow < NN) ? 16 : 0);
        }
        const uint4* wh = (const uint4*)(g_Wh + c * 16384);
        uint32_t bbase = abase + 16384;
        #pragma unroll
        for (int it = 0; it < 4; it++) {
            int i = tid + it * 256;
            CP_ASYNC16(bbase + i * 16, wh + i, 16);
        }
    };

    float acc[2][8][4];
    #pragma unroll
    for (int mf = 0; mf < 2; mf++)
        #pragma unroll
        for (int nf = 0; nf < 8; nf++)
            #pragma unroll
            for (int q = 0; q < 4; q++) acc[mf][nf][q] = 0.f;

    const int g = lane >> 3, r = lane & 7;
    const int a_row_off = r + (g & 1) * 8;
    const int a_k_off   = (g >> 1) * 8;
    const int b_n_off   = r + (g >> 1) * 8;
    const int b_k_off   = (g & 1) * 8;

    issue_chunk(0, 0);
    CP_COMMIT();

    #pragma unroll
    for (int c = 0; c < 6; c++) {
        if (c < 5) {
            issue_chunk(c + 1, (c + 1) & 1);
            CP_COMMIT();
            CP_WAIT(1);
        } else {
            CP_WAIT(0);
        }
        __syncthreads();
        const uint32_t At = base + (c & 1) * STAGE_BYTES;
        const uint32_t Bh = At + 16384;
        #pragma unroll
        for (int ks = 0; ks < 4; ks++) {
            const int k0 = ks * 16;
            uint32_t ah[2][4];
            #pragma unroll
            for (int mf = 0; mf < 2; mf++) {
                uint32_t sw = swz((uint32_t)(warp_m * 32 + mf * 16 + a_row_off) * 128
                                  + (k0 + a_k_off) * 2);
                LDSM4(ah[mf], At + sw);
            }
            #pragma unroll
            for (int bq = 0; bq < 4; bq++) {
                uint32_t sw = swz((uint32_t)(warp_n * 64 + bq * 16 + b_n_off) * 128
                                  + (k0 + b_k_off) * 2);
                uint32_t bh[4];
                LDSM4(bh, Bh + sw);
                #pragma unroll
                for (int mf = 0; mf < 2; mf++) {
                    MMAF16(acc[mf][bq * 2 + 0], ah[mf], bh[0], bh[1]);
                    MMAF16(acc[mf][bq * 2 + 1], ah[mf], bh[2], bh[3]);
                }
            }
        }
        __syncthreads();
    }

    // ---- epilogue: bias + store ----
    const int qrow = lane >> 2, qcol = (lane & 3) * 2;
    #pragma unroll
    for (int nf = 0; nf < 8; nf++) {
        int col = warp_n * 64 + nf * 8 + qcol;
        float b0 = __ldg(&bias[col]);
        float b1 = __ldg(&bias[col + 1]);
        #pragma unroll
        for (int mf = 0; mf < 2; mf++) {
            int row0 = rbase + warp_m * 32 + mf * 16 + qrow;
            if (row0 < NN)
                *(float2*)(out + (size_t)row0 * 128 + col) =
                    make_float2(acc[mf][nf][0] + b0, acc[mf][nf][1] + b1);
            int row1 = row0 + 8;
            if (row1 < NN)
                *(float2*)(out + (size_t)row1 * 128 + col) =
                    make_float2(acc[mf][nf][2] + b0, acc[mf][nf][3] + b1);
        }
    }
}

// ---------------- launch ------------------------------------------------------
extern "C" void kernel_launch(void* const* d_in, const int* in_sizes, int n_in,
                              void* d_out, int out_size) {
    const float* x        = (const float*)d_in[0];
    const int*   edge_src = (const int*)  d_in[1];
    const int*   edge_dst = (const int*)  d_in[2];
    const float* edge_val = (const float*)d_in[3];
    const float* W        = (const float*)d_in[4];
    const float* b        = (const float*)d_in[5];
    float* out = (float*)d_out;

    static bool attr_set = false;
    static void* degp = nullptr;
    if (!attr_set) {
        cudaFuncSetAttribute(gemm_mma_kernel,
                             cudaFuncAttributeMaxDynamicSharedMemorySize,
                             SMEM_GEMM_BYTES);
        cudaGetSymbolAddress(&degp, g_deg);
        attr_set = true;
    }

    uint4 *xhp, *f1p, *f2p;
    cudaGetSymbolAddress((void**)&xhp, g_xh);
    cudaGetSymbolAddress((void**)&f1p, g_f1);
    cudaGetSymbolAddress((void**)&f2p, g_f2);

    // 1) memset deg, fused prep (conversions + histogram/rank), scan, scatter
    cudaMemsetAsync(degp, 0, NN * sizeof(int));
    prep_hist_kernel<<<XBLOCKS + WBLOCKS + HBLOCKS, 256>>>((const float4*)x, W,
                                                           edge_src);
    scan_local_kernel<<<NB, 1024>>>();
    scan_add_kernel<<<(NN + 255) / 256, 256>>>();
    scatter_kernel<<<(EE / 4 + 255) / 256, 256>>>(edge_src, edge_dst, edge_val);

    // 2) Two SpMM hops (fp16 gather, fp32 accumulate) — half-warp per row
    int spmm_blocks = (NN + 15) / 16;
    spmm_kernel<<<spmm_blocks, 256>>>(xhp, f1p);
    spmm_kernel<<<spmm_blocks, 256>>>(f1p, f2p);

    // 3) Tensor-core dense layer, cp.async double-buffered
    gemm_mma_kernel<<<(NN + 127) / 128, 256, SMEM_GEMM_BYTES>>>(b, out);
}